// round 12
// baseline (speedup 1.0000x reference)
#include <cuda_runtime.h>
#include <cuda_bf16.h>
#include <cstdint>

#define XN 16777216   // 16*32*32*1024
#define WN 1048576    // 1024*1024

__device__ __nv_bfloat16 g_x1h[XN], g_x1l[XN], g_x2h[XN], g_x2l[XN];
__device__ __nv_bfloat16 g_wh[3 * WN], g_wl[3 * WN];   // W[n][k] split (no transpose)
__device__ float g_Yq[XN], g_Yk[XN], g_Yv[XN], g_O[XN];

// ============ helpers ============
__device__ __forceinline__ unsigned smem_u32(const void* p) {
    return (unsigned)__cvta_generic_to_shared(p);
}
__device__ __forceinline__ void cpasync16(unsigned s, const void* g) {
    asm volatile("cp.async.cg.shared.global [%0], [%1], 16;" :: "r"(s), "l"(g));
}
__device__ __forceinline__ void cpasync_commit() {
    asm volatile("cp.async.commit_group;");
}
template <int N>
__device__ __forceinline__ void cpasync_wait() {
    asm volatile("cp.async.wait_group %0;" :: "n"(N));
}
__device__ __forceinline__ void ldsm4(unsigned* r, unsigned addr) {
    asm volatile("ldmatrix.sync.aligned.m8n8.x4.shared.b16 {%0,%1,%2,%3}, [%4];"
                 : "=r"(r[0]), "=r"(r[1]), "=r"(r[2]), "=r"(r[3]) : "r"(addr));
}
__device__ __forceinline__ void mma_bf16(float* d, const unsigned* a, unsigned b0, unsigned b1) {
    asm volatile(
        "mma.sync.aligned.m16n8k16.row.col.f32.bf16.bf16.f32 "
        "{%0,%1,%2,%3}, {%4,%5,%6,%7}, {%8,%9}, {%0,%1,%2,%3};"
        : "+f"(d[0]), "+f"(d[1]), "+f"(d[2]), "+f"(d[3])
        : "r"(a[0]), "r"(a[1]), "r"(a[2]), "r"(a[3]), "r"(b0), "r"(b1));
}

// ============ 1) split activations fp32 -> (hi,lo) bf16 ============
__global__ void split_x_kernel(const float* __restrict__ x, int which) {
    int i = blockIdx.x * blockDim.x + threadIdx.x;   // float4 index
    float4 v = reinterpret_cast<const float4*>(x)[i];
    __nv_bfloat16* __restrict__ h = which ? g_x2h : g_x1h;
    __nv_bfloat16* __restrict__ l = which ? g_x2l : g_x1l;
    __nv_bfloat16 h0 = __float2bfloat16(v.x), h1 = __float2bfloat16(v.y);
    __nv_bfloat16 h2 = __float2bfloat16(v.z), h3 = __float2bfloat16(v.w);
    __nv_bfloat16 l0 = __float2bfloat16(v.x - __bfloat162float(h0));
    __nv_bfloat16 l1 = __float2bfloat16(v.y - __bfloat162float(h1));
    __nv_bfloat16 l2 = __float2bfloat16(v.z - __bfloat162float(h2));
    __nv_bfloat16 l3 = __float2bfloat16(v.w - __bfloat162float(h3));
    __nv_bfloat162* hp = reinterpret_cast<__nv_bfloat162*>(h) + 2 * i;
    __nv_bfloat162* lp = reinterpret_cast<__nv_bfloat162*>(l) + 2 * i;
    hp[0] = __halves2bfloat162(h0, h1); hp[1] = __halves2bfloat162(h2, h3);
    lp[0] = __halves2bfloat162(l0, l1); lp[1] = __halves2bfloat162(l2, l3);
}

// ============ 2) split weights flat (W[n][k] is already col-major B) ============
__global__ void wsplit_flat(const float* __restrict__ W, int wi) {
    int i = blockIdx.x * blockDim.x + threadIdx.x;   // float4 index
    float4 v = reinterpret_cast<const float4*>(W)[i];
    __nv_bfloat16* __restrict__ h = g_wh + wi * WN;
    __nv_bfloat16* __restrict__ l = g_wl + wi * WN;
    __nv_bfloat16 h0 = __float2bfloat16(v.x), h1 = __float2bfloat16(v.y);
    __nv_bfloat16 h2 = __float2bfloat16(v.z), h3 = __float2bfloat16(v.w);
    __nv_bfloat16 l0 = __float2bfloat16(v.x - __bfloat162float(h0));
    __nv_bfloat16 l1 = __float2bfloat16(v.y - __bfloat162float(h1));
    __nv_bfloat16 l2 = __float2bfloat16(v.z - __bfloat162float(h2));
    __nv_bfloat16 l3 = __float2bfloat16(v.w - __bfloat162float(h3));
    __nv_bfloat162* hp = reinterpret_cast<__nv_bfloat162*>(h) + 2 * i;
    __nv_bfloat162* lp = reinterpret_cast<__nv_bfloat162*>(l) + 2 * i;
    hp[0] = __halves2bfloat162(h0, h1); hp[1] = __halves2bfloat162(h2, h3);
    lp[0] = __halves2bfloat162(l0, l1); lp[1] = __halves2bfloat162(l2, l3);
}

// ============ 3) GEMM Y[m][n] = sum_k X[m][k]*W[n][k], bf16x3 mma.sync ============
// smem: 2 stages x 4 arrays (Ah,Al,Bh,Bl), each 128 rows x 40 bf16 (80 B rows)
#define ROWB 80
#define ARR_B 10240
#define STG_B 40960   // 4 arrays
// total 2*STG_B = 81920 bytes

extern __shared__ __nv_bfloat16 dyn_smem[];

__global__ void __launch_bounds__(256) gemm_mma_kernel() {
    int z = blockIdx.z;
    const __nv_bfloat16* Ah = (z == 0) ? g_x1h : g_x2h;
    const __nv_bfloat16* Al = (z == 0) ? g_x1l : g_x2l;
    const __nv_bfloat16* Bh = g_wh + z * WN;
    const __nv_bfloat16* Bl = g_wl + z * WN;
    float* Y = (z == 0) ? g_Yq : ((z == 1) ? g_Yk : g_Yv);

    int t = threadIdx.x, warp = t >> 5, lane = t & 31;
    int wm = warp & 3, wn = warp >> 2;               // m-slab 32, n-slab 64
    int rb = blockIdx.y * 128, cb = blockIdx.x * 128;

    unsigned sb = smem_u32(dyn_smem);

    float acc[2][8][4];
#pragma unroll
    for (int mi = 0; mi < 2; mi++)
#pragma unroll
        for (int nj = 0; nj < 8; nj++)
#pragma unroll
            for (int q = 0; q < 4; q++) acc[mi][nj][q] = 0.f;

    // staging map: idx = t + i*256; row = idx>>2 (0..127), chunk = idx&3 (16B each)
    int r0 = t >> 2, c0 = t & 3;
    int r1 = (t + 256) >> 2, c1 = (t + 256) & 3;
    const __nv_bfloat16* gAh0 = Ah + (rb + r0) * 1024 + c0 * 8;
    const __nv_bfloat16* gAl0 = Al + (rb + r0) * 1024 + c0 * 8;
    const __nv_bfloat16* gBh0 = Bh + (cb + r0) * 1024 + c0 * 8;
    const __nv_bfloat16* gBl0 = Bl + (cb + r0) * 1024 + c0 * 8;
    const __nv_bfloat16* gAh1 = Ah + (rb + r1) * 1024 + c1 * 8;
    const __nv_bfloat16* gAl1 = Al + (rb + r1) * 1024 + c1 * 8;
    const __nv_bfloat16* gBh1 = Bh + (cb + r1) * 1024 + c1 * 8;
    const __nv_bfloat16* gBl1 = Bl + (cb + r1) * 1024 + c1 * 8;
    unsigned s0 = (unsigned)(r0 * ROWB + c0 * 16);
    unsigned s1 = (unsigned)(r1 * ROWB + c1 * 16);

#define STAGE(buf, kt)                                                    \
    do {                                                                  \
        int _kc = (kt) * 32;                                              \
        unsigned _b = sb + (buf) * STG_B;                                 \
        cpasync16(_b + 0 * ARR_B + s0, gAh0 + _kc);                       \
        cpasync16(_b + 1 * ARR_B + s0, gAl0 + _kc);                       \
        cpasync16(_b + 2 * ARR_B + s0, gBh0 + _kc);                       \
        cpasync16(_b + 3 * ARR_B + s0, gBl0 + _kc);                       \
        cpasync16(_b + 0 * ARR_B + s1, gAh1 + _kc);                       \
        cpasync16(_b + 1 * ARR_B + s1, gAl1 + _kc);                       \
        cpasync16(_b + 2 * ARR_B + s1, gBh1 + _kc);                       \
        cpasync16(_b + 3 * ARR_B + s1, gBl1 + _kc);                       \
        cpasync_commit();                                                 \
    } while (0)

    // ldmatrix per-thread address components
    unsigned aRowB = (unsigned)((lane & 15) * ROWB);
    unsigned aColB = (unsigned)((lane >> 4) * 16);
    unsigned bRowB = (unsigned)(((((lane >> 4) & 1) * 8) + (lane & 7)) * ROWB);
    unsigned bColB = (unsigned)(((lane >> 3) & 1) * 16);

    STAGE(0, 0);

    for (int kt = 0; kt < 32; kt++) {
        int buf = kt & 1;
        if (kt + 1 < 32) {
            STAGE(buf ^ 1, kt + 1);
            cpasync_wait<1>();
        } else {
            cpasync_wait<0>();
        }
        __syncthreads();

        unsigned base = sb + buf * STG_B;
#pragma unroll
        for (int k16 = 0; k16 < 2; k16++) {
            unsigned kOff = (unsigned)(k16 * 32);
            unsigned ah[2][4], al[2][4];
#pragma unroll
            for (int mi = 0; mi < 2; mi++) {
                unsigned ad = base + (unsigned)((wm * 32 + mi * 16) * ROWB) + aRowB + kOff + aColB;
                ldsm4(ah[mi], ad);               // Ah array
                ldsm4(al[mi], ad + ARR_B);       // Al array
            }
#pragma unroll
            for (int np = 0; np < 4; np++) {     // pairs of n-tiles
                unsigned bd = base + 2 * ARR_B + (unsigned)((wn * 64 + np * 16) * ROWB)
                            + bRowB + kOff + bColB;
                unsigned bh[4], bl[4];
                ldsm4(bh, bd);                   // Bh array
                ldsm4(bl, bd + ARR_B);           // Bl array
#pragma unroll
                for (int mi = 0; mi < 2; mi++) {
#pragma unroll
                    for (int nt = 0; nt < 2; nt++) {
                        float* d = acc[mi][np * 2 + nt];
                        mma_bf16(d, ah[mi], bh[nt * 2], bh[nt * 2 + 1]);
                        mma_bf16(d, ah[mi], bl[nt * 2], bl[nt * 2 + 1]);
                        mma_bf16(d, al[mi], bh[nt * 2], bh[nt * 2 + 1]);
                    }
                }
            }
        }
        __syncthreads();
    }

    // epilogue: fragment c0,c1 = (row lane/4, col 2*(lane%4)+{0,1}); c2,c3 = row+8
    int erow = lane >> 2, ecol = (lane & 3) * 2;
#pragma unroll
    for (int mi = 0; mi < 2; mi++) {
#pragma unroll
        for (int nj = 0; nj < 8; nj++) {
            int gr = rb + wm * 32 + mi * 16 + erow;
            int gc = cb + wn * 64 + nj * 8 + ecol;
            float2 v01 = make_float2(acc[mi][nj][0], acc[mi][nj][1]);
            float2 v23 = make_float2(acc[mi][nj][2], acc[mi][nj][3]);
            *reinterpret_cast<float2*>(Y + gr * 1024 + gc) = v01;
            *reinterpret_cast<float2*>(Y + (gr + 8) * 1024 + gc) = v23;
        }
    }
}

// ============ 4) attention: warp per unit (b,i,j); lane = l2 column ============
__global__ void __launch_bounds__(128) attn_kernel(const float* __restrict__ bq,
                                                   const float* __restrict__ bk,
                                                   const float* __restrict__ bv) {
    __shared__ float qs[4][32][33];
    __shared__ float vs[4][32][33];
    int w = threadIdx.x >> 5, lane = threadIdx.x & 31;
    int u = blockIdx.x * 4 + w;
    int b = u >> 10, i = (u >> 5) & 31, j = u & 31;

    const float* Krow = g_Yk + ((b * 32 + i) * 32 + j) * 1024;
    const float* Vrow = g_Yv + ((b * 32 + i) * 32 + j) * 1024;

    float kreg[32];
#pragma unroll
    for (int h = 0; h < 32; h++)
        kreg[h] = Krow[h * 32 + lane] + bk[h * 32 + lane];
#pragma unroll
    for (int r = 0; r < 32; r++)
        vs[w][r][lane] = Vrow[r * 32 + lane] + bv[r * 32 + lane];
#pragma unroll
    for (int r = 0; r < 32; r++)
        qs[w][r][lane] = g_Yq[((b * 32 + lane) * 32 + i) * 1024 + r * 32 + j] + bq[r * 32 + j];
    __syncwarp();

    float a[32];
#pragma unroll
    for (int r = 0; r < 32; r++) {
        float e = 0.f;
#pragma unroll
        for (int h = 0; h < 32; h++) e = fmaf(qs[w][r][h], kreg[h], e);
        float m = e;
#pragma unroll
        for (int o = 16; o > 0; o >>= 1) m = fmaxf(m, __shfl_xor_sync(0xffffffffu, m, o));
        float p = __expf(e - m);
        float s = p;
#pragma unroll
        for (int o = 16; o > 0; o >>= 1) s += __shfl_xor_sync(0xffffffffu, s, o);
        a[r] = p * __frcp_rn(s);
    }

    float* Orow = g_O + ((b * 32 + i) * 32 + j) * 1024;
#pragma unroll
    for (int r = 0; r < 32; r++) {
        float o = 0.f;
#pragma unroll
        for (int t = 0; t < 32; t++) o = fmaf(vs[w][r][t], a[t], o);
        Orow[r * 32 + lane] = o;
    }
}

// ============ 5) output transpose: out[b,j,l, r*32+i] = g_O[b,i,j, r*32+l] ============
__global__ void otrans_kernel(float* __restrict__ out) {
    __shared__ float s[32][33];
    int t = threadIdx.x;
    int b = blockIdx.x >> 5, j = blockIdx.x & 31;
    for (int r = 0; r < 32; r++) {
        __syncthreads();
#pragma unroll
        for (int k = 0; k < 4; k++) {
            int idx = t + k * 256, i = idx >> 5, l = idx & 31;
            s[i][l] = g_O[((b * 32 + i) * 32 + j) * 1024 + r * 32 + l];
        }
        __syncthreads();
#pragma unroll
        for (int k = 0; k < 4; k++) {
            int idx = t + k * 256, l = idx >> 5, i = idx & 31;
            out[((b * 32 + j) * 32 + l) * 1024 + r * 32 + i] = s[i][l];
        }
    }
}

extern "C" void kernel_launch(void* const* d_in, const int* in_sizes, int n_in,
                              void* d_out, int out_size) {
    const float* x1 = (const float*)d_in[0];
    const float* x2 = (const float*)d_in[1];
    const float* Wq = (const float*)d_in[2];
    const float* bq = (const float*)d_in[3];
    const float* Wk = (const float*)d_in[4];
    const float* bk = (const float*)d_in[5];
    const float* Wv = (const float*)d_in[6];
    const float* bv = (const float*)d_in[7];
    float* out = (float*)d_out;

    cudaFuncSetAttribute(gemm_mma_kernel, cudaFuncAttributeMaxDynamicSharedMemorySize, 2 * STG_B);

    split_x_kernel<<<16384, 256>>>(x1, 0);
    split_x_kernel<<<16384, 256>>>(x2, 1);
    wsplit_flat<<<1024, 256>>>(Wq, 0);
    wsplit_flat<<<1024, 256>>>(Wk, 1);
    wsplit_flat<<<1024, 256>>>(Wv, 2);
    gemm_mma_kernel<<<dim3(8, 128, 3), 256, 2 * STG_B>>>();
    attn_kernel<<<4096, 128>>>(bq, bk, bv);
    otrans_kernel<<<512, 256>>>(out);
}

// round 16
// speedup vs baseline: 1.5554x; 1.5554x over previous
#include <cuda_runtime.h>
#include <cuda_bf16.h>
#include <cstdint>

#define XN 16777216   // 16*32*32*1024
#define WN 1048576    // 1024*1024

__device__ __nv_bfloat16 g_x1h[XN], g_x1l[XN], g_x2h[XN], g_x2l[XN];
__device__ __nv_bfloat16 g_wh[3 * WN], g_wl[3 * WN];   // W[n][k] split (no transpose)
__device__ float g_Yq[XN], g_Yk[XN], g_Yv[XN], g_O[XN];

// ============ helpers ============
__device__ __forceinline__ unsigned smem_u32(const void* p) {
    return (unsigned)__cvta_generic_to_shared(p);
}
__device__ __forceinline__ void cpasync16(unsigned s, const void* g) {
    asm volatile("cp.async.cg.shared.global [%0], [%1], 16;" :: "r"(s), "l"(g));
}
__device__ __forceinline__ void cpasync_commit() {
    asm volatile("cp.async.commit_group;");
}
template <int N>
__device__ __forceinline__ void cpasync_wait() {
    asm volatile("cp.async.wait_group %0;" :: "n"(N));
}
__device__ __forceinline__ void ldsm4(unsigned* r, unsigned addr) {
    asm volatile("ldmatrix.sync.aligned.m8n8.x4.shared.b16 {%0,%1,%2,%3}, [%4];"
                 : "=r"(r[0]), "=r"(r[1]), "=r"(r[2]), "=r"(r[3]) : "r"(addr));
}
__device__ __forceinline__ void mma_bf16(float* d, const unsigned* a, unsigned b0, unsigned b1) {
    asm volatile(
        "mma.sync.aligned.m16n8k16.row.col.f32.bf16.bf16.f32 "
        "{%0,%1,%2,%3}, {%4,%5,%6,%7}, {%8,%9}, {%0,%1,%2,%3};"
        : "+f"(d[0]), "+f"(d[1]), "+f"(d[2]), "+f"(d[3])
        : "r"(a[0]), "r"(a[1]), "r"(a[2]), "r"(a[3]), "r"(b0), "r"(b1));
}

// ============ 1) split activations fp32 -> (hi,lo) bf16 ============
__global__ void split_x_kernel(const float* __restrict__ x, int which) {
    int i = blockIdx.x * blockDim.x + threadIdx.x;   // float4 index
    float4 v = reinterpret_cast<const float4*>(x)[i];
    __nv_bfloat16* __restrict__ h = which ? g_x2h : g_x1h;
    __nv_bfloat16* __restrict__ l = which ? g_x2l : g_x1l;
    __nv_bfloat16 h0 = __float2bfloat16(v.x), h1 = __float2bfloat16(v.y);
    __nv_bfloat16 h2 = __float2bfloat16(v.z), h3 = __float2bfloat16(v.w);
    __nv_bfloat16 l0 = __float2bfloat16(v.x - __bfloat162float(h0));
    __nv_bfloat16 l1 = __float2bfloat16(v.y - __bfloat162float(h1));
    __nv_bfloat16 l2 = __float2bfloat16(v.z - __bfloat162float(h2));
    __nv_bfloat16 l3 = __float2bfloat16(v.w - __bfloat162float(h3));
    __nv_bfloat162* hp = reinterpret_cast<__nv_bfloat162*>(h) + 2 * i;
    __nv_bfloat162* lp = reinterpret_cast<__nv_bfloat162*>(l) + 2 * i;
    hp[0] = __halves2bfloat162(h0, h1); hp[1] = __halves2bfloat162(h2, h3);
    lp[0] = __halves2bfloat162(l0, l1); lp[1] = __halves2bfloat162(l2, l3);
}

// ============ 2) split weights flat (W[n][k] is already col-major B) ============
__global__ void wsplit_flat(const float* __restrict__ W, int wi) {
    int i = blockIdx.x * blockDim.x + threadIdx.x;   // float4 index
    float4 v = reinterpret_cast<const float4*>(W)[i];
    __nv_bfloat16* __restrict__ h = g_wh + wi * WN;
    __nv_bfloat16* __restrict__ l = g_wl + wi * WN;
    __nv_bfloat16 h0 = __float2bfloat16(v.x), h1 = __float2bfloat16(v.y);
    __nv_bfloat16 h2 = __float2bfloat16(v.z), h3 = __float2bfloat16(v.w);
    __nv_bfloat16 l0 = __float2bfloat16(v.x - __bfloat162float(h0));
    __nv_bfloat16 l1 = __float2bfloat16(v.y - __bfloat162float(h1));
    __nv_bfloat16 l2 = __float2bfloat16(v.z - __bfloat162float(h2));
    __nv_bfloat16 l3 = __float2bfloat16(v.w - __bfloat162float(h3));
    __nv_bfloat162* hp = reinterpret_cast<__nv_bfloat162*>(h) + 2 * i;
    __nv_bfloat162* lp = reinterpret_cast<__nv_bfloat162*>(l) + 2 * i;
    hp[0] = __halves2bfloat162(h0, h1); hp[1] = __halves2bfloat162(h2, h3);
    lp[0] = __halves2bfloat162(l0, l1); lp[1] = __halves2bfloat162(l2, l3);
}

// ============ 3) GEMM Y[m][n] = sum_k X[m][k]*W[n][k], bf16x3 mma.sync ============
// 512 threads, warp tile 32x32, 3-stage cp.async ring.
// smem per stage: 4 arrays (Ah,Al,Bh,Bl), each 128 rows x 40 bf16 (80B pitch)
#define ROWB 80
#define ARR_B 10240
#define STG_B 40960
#define NSTAGE 3
// total = 3*40960 = 122880 bytes

extern __shared__ __nv_bfloat16 dyn_smem[];

__global__ void __launch_bounds__(512, 1) gemm_mma_kernel() {
    int z = blockIdx.z;
    const __nv_bfloat16* Ah = (z == 0) ? g_x1h : g_x2h;
    const __nv_bfloat16* Al = (z == 0) ? g_x1l : g_x2l;
    const __nv_bfloat16* Bh = g_wh + z * WN;
    const __nv_bfloat16* Bl = g_wl + z * WN;
    float* Y = (z == 0) ? g_Yq : ((z == 1) ? g_Yk : g_Yv);

    int t = threadIdx.x, warp = t >> 5, lane = t & 31;
    int wm = warp & 3, wn = warp >> 2;               // 4x4 warp grid, 32x32 tiles
    int rb = blockIdx.y * 128, cb = blockIdx.x * 128;

    unsigned sb = smem_u32(dyn_smem);

    float acc[2][4][4];
#pragma unroll
    for (int mi = 0; mi < 2; mi++)
#pragma unroll
        for (int nj = 0; nj < 4; nj++)
#pragma unroll
            for (int q = 0; q < 4; q++) acc[mi][nj][q] = 0.f;

    // staging: each thread copies one 16B chunk per array per stage
    int sr = t >> 2, sc = t & 3;                     // row 0..127, chunk 0..3
    const __nv_bfloat16* gA0 = Ah + (rb + sr) * 1024 + sc * 8;
    const __nv_bfloat16* gA1 = Al + (rb + sr) * 1024 + sc * 8;
    const __nv_bfloat16* gB0 = Bh + (cb + sr) * 1024 + sc * 8;
    const __nv_bfloat16* gB1 = Bl + (cb + sr) * 1024 + sc * 8;
    unsigned sdst = (unsigned)(sr * ROWB + sc * 16);

#define STAGE(buf, kt)                                   \
    do {                                                 \
        int _kc = (kt) * 32;                             \
        unsigned _b = sb + (buf) * STG_B + sdst;         \
        cpasync16(_b + 0 * ARR_B, gA0 + _kc);            \
        cpasync16(_b + 1 * ARR_B, gA1 + _kc);            \
        cpasync16(_b + 2 * ARR_B, gB0 + _kc);            \
        cpasync16(_b + 3 * ARR_B, gB1 + _kc);            \
        cpasync_commit();                                \
    } while (0)

    // ldmatrix per-lane address components (identical mapping to R12, which passed)
    unsigned aRowB = (unsigned)((lane & 15) * ROWB);
    unsigned aColB = (unsigned)((lane >> 4) * 16);
    unsigned bRowB = (unsigned)(((((lane >> 4) & 1) * 8) + (lane & 7)) * ROWB);
    unsigned bColB = (unsigned)(((lane >> 3) & 1) * 16);

    STAGE(0, 0); STAGE(1, 1); STAGE(2, 2);

    for (int kt = 0; kt < 32; kt++) {
        int buf = kt % 3;
        if (kt < 30)       cpasync_wait<2>();
        else if (kt == 30) cpasync_wait<1>();
        else               cpasync_wait<0>();
        __syncthreads();

        unsigned base = sb + buf * STG_B;
#pragma unroll
        for (int k16 = 0; k16 < 2; k16++) {
            unsigned kOff = (unsigned)(k16 * 32);
            unsigned ah[2][4], al[2][4], bh[2][4], bl[2][4];
#pragma unroll
            for (int mi = 0; mi < 2; mi++) {
                unsigned ad = base + (unsigned)((wm * 32 + mi * 16) * ROWB) + aRowB + kOff + aColB;
                ldsm4(ah[mi], ad);
                ldsm4(al[mi], ad + ARR_B);
            }
#pragma unroll
            for (int nt = 0; nt < 2; nt++) {
                unsigned bd = base + 2 * ARR_B + (unsigned)((wn * 32 + nt * 16) * ROWB)
                            + bRowB + kOff + bColB;
                ldsm4(bh[nt], bd);
                ldsm4(bl[nt], bd + ARR_B);
            }
            // term-major: 8 independent MMAs per term -> dependency distance 8
#pragma unroll
            for (int mi = 0; mi < 2; mi++)
#pragma unroll
                for (int nj = 0; nj < 4; nj++)
                    mma_bf16(acc[mi][nj], ah[mi], bh[nj >> 1][(nj & 1) * 2], bh[nj >> 1][(nj & 1) * 2 + 1]);
#pragma unroll
            for (int mi = 0; mi < 2; mi++)
#pragma unroll
                for (int nj = 0; nj < 4; nj++)
                    mma_bf16(acc[mi][nj], ah[mi], bl[nj >> 1][(nj & 1) * 2], bl[nj >> 1][(nj & 1) * 2 + 1]);
#pragma unroll
            for (int mi = 0; mi < 2; mi++)
#pragma unroll
                for (int nj = 0; nj < 4; nj++)
                    mma_bf16(acc[mi][nj], al[mi], bh[nj >> 1][(nj & 1) * 2], bh[nj >> 1][(nj & 1) * 2 + 1]);
        }
        __syncthreads();
        if (kt + 3 < 32) STAGE(buf, kt + 3);
    }

    // epilogue: c0,c1 = (row lane/4, col 2*(lane%4)); c2,c3 = row+8
    int erow = lane >> 2, ecol = (lane & 3) * 2;
#pragma unroll
    for (int mi = 0; mi < 2; mi++) {
#pragma unroll
        for (int nj = 0; nj < 4; nj++) {
            int gr = rb + wm * 32 + mi * 16 + erow;
            int gc = cb + wn * 32 + nj * 8 + ecol;
            *reinterpret_cast<float2*>(Y + gr * 1024 + gc) =
                make_float2(acc[mi][nj][0], acc[mi][nj][1]);
            *reinterpret_cast<float2*>(Y + (gr + 8) * 1024 + gc) =
                make_float2(acc[mi][nj][2], acc[mi][nj][3]);
        }
    }
}

// ============ 4) attention: warp per unit (b,i,j); lane = l2 column ============
__global__ void __launch_bounds__(128) attn_kernel(const float* __restrict__ bq,
                                                   const float* __restrict__ bk,
                                                   const float* __restrict__ bv) {
    __shared__ float qs[4][32][33];
    __shared__ float vs[4][32][33];
    int w = threadIdx.x >> 5, lane = threadIdx.x & 31;
    int u = blockIdx.x * 4 + w;
    int b = u >> 10, i = (u >> 5) & 31, j = u & 31;

    const float* Krow = g_Yk + ((b * 32 + i) * 32 + j) * 1024;
    const float* Vrow = g_Yv + ((b * 32 + i) * 32 + j) * 1024;

    float kreg[32];
#pragma unroll
    for (int h = 0; h < 32; h++)
        kreg[h] = Krow[h * 32 + lane] + bk[h * 32 + lane];
#pragma unroll
    for (int r = 0; r < 32; r++)
        vs[w][r][lane] = Vrow[r * 32 + lane] + bv[r * 32 + lane];
#pragma unroll
    for (int r = 0; r < 32; r++)
        qs[w][r][lane] = g_Yq[((b * 32 + lane) * 32 + i) * 1024 + r * 32 + j] + bq[r * 32 + j];
    __syncwarp();

    float a[32];
#pragma unroll
    for (int r = 0; r < 32; r++) {
        float e = 0.f;
#pragma unroll
        for (int h = 0; h < 32; h++) e = fmaf(qs[w][r][h], kreg[h], e);
        float m = e;
#pragma unroll
        for (int o = 16; o > 0; o >>= 1) m = fmaxf(m, __shfl_xor_sync(0xffffffffu, m, o));
        float p = __expf(e - m);
        float s = p;
#pragma unroll
        for (int o = 16; o > 0; o >>= 1) s += __shfl_xor_sync(0xffffffffu, s, o);
        a[r] = p * __frcp_rn(s);
    }

    float* Orow = g_O + ((b * 32 + i) * 32 + j) * 1024;
#pragma unroll
    for (int r = 0; r < 32; r++) {
        float o = 0.f;
#pragma unroll
        for (int t = 0; t < 32; t++) o = fmaf(vs[w][r][t], a[t], o);
        Orow[r * 32 + lane] = o;
    }
}

// ============ 5) output transpose: out[b,j,l, r*32+i] = g_O[b,i,j, r*32+l] ============
__global__ void otrans_kernel(float* __restrict__ out) {
    __shared__ float s[32][33];
    int t = threadIdx.x;
    int b = blockIdx.x >> 5, j = blockIdx.x & 31;
    for (int r = 0; r < 32; r++) {
        __syncthreads();
#pragma unroll
        for (int k = 0; k < 4; k++) {
            int idx = t + k * 256, i = idx >> 5, l = idx & 31;
            s[i][l] = g_O[((b * 32 + i) * 32 + j) * 1024 + r * 32 + l];
        }
        __syncthreads();
#pragma unroll
        for (int k = 0; k < 4; k++) {
            int idx = t + k * 256, l = idx >> 5, i = idx & 31;
            out[((b * 32 + j) * 32 + l) * 1024 + r * 32 + i] = s[i][l];
        }
    }
}

extern "C" void kernel_launch(void* const* d_in, const int* in_sizes, int n_in,
                              void* d_out, int out_size) {
    const float* x1 = (const float*)d_in[0];
    const float* x2 = (const float*)d_in[1];
    const float* Wq = (const float*)d_in[2];
    const float* bq = (const float*)d_in[3];
    const float* Wk = (const float*)d_in[4];
    const float* bk = (const float*)d_in[5];
    const float* Wv = (const float*)d_in[6];
    const float* bv = (const float*)d_in[7];
    float* out = (float*)d_out;

    cudaFuncSetAttribute(gemm_mma_kernel, cudaFuncAttributeMaxDynamicSharedMemorySize,
                         NSTAGE * STG_B);

    split_x_kernel<<<16384, 256>>>(x1, 0);
    split_x_kernel<<<16384, 256>>>(x2, 1);
    wsplit_flat<<<1024, 256>>>(Wq, 0);
    wsplit_flat<<<1024, 256>>>(Wk, 1);
    wsplit_flat<<<1024, 256>>>(Wv, 2);
    gemm_mma_kernel<<<dim3(8, 128, 3), 512, NSTAGE * STG_B>>>();
    attn_kernel<<<4096, 128>>>(bq, bk, bv);
    otrans_kernel<<<512, 256>>>(out);
}

// round 17
// speedup vs baseline: 1.6126x; 1.0368x over previous
#include <cuda_runtime.h>
#include <cuda_bf16.h>
#include <cstdint>

#define XN 16777216   // 16*32*32*1024
#define WN 1048576    // 1024*1024

__device__ __nv_bfloat16 g_x1h[XN], g_x1l[XN], g_x2h[XN], g_x2l[XN];
__device__ __nv_bfloat16 g_wh[3 * WN], g_wl[3 * WN];   // W[n][k] split (no transpose)
__device__ float g_Yq[XN], g_Yk[XN], g_Yv[XN], g_O[XN];

// ============ helpers ============
__device__ __forceinline__ unsigned smem_u32(const void* p) {
    return (unsigned)__cvta_generic_to_shared(p);
}
__device__ __forceinline__ void cpasync16(unsigned s, const void* g) {
    asm volatile("cp.async.cg.shared.global [%0], [%1], 16;" :: "r"(s), "l"(g));
}
__device__ __forceinline__ void cpasync_commit() {
    asm volatile("cp.async.commit_group;");
}
template <int N>
__device__ __forceinline__ void cpasync_wait() {
    asm volatile("cp.async.wait_group %0;" :: "n"(N));
}
__device__ __forceinline__ void ldsm4(unsigned* r, unsigned addr) {
    asm volatile("ldmatrix.sync.aligned.m8n8.x4.shared.b16 {%0,%1,%2,%3}, [%4];"
                 : "=r"(r[0]), "=r"(r[1]), "=r"(r[2]), "=r"(r[3]) : "r"(addr));
}
__device__ __forceinline__ void mma_bf16(float* d, const unsigned* a, unsigned b0, unsigned b1) {
    asm volatile(
        "mma.sync.aligned.m16n8k16.row.col.f32.bf16.bf16.f32 "
        "{%0,%1,%2,%3}, {%4,%5,%6,%7}, {%8,%9}, {%0,%1,%2,%3};"
        : "+f"(d[0]), "+f"(d[1]), "+f"(d[2]), "+f"(d[3])
        : "r"(a[0]), "r"(a[1]), "r"(a[2]), "r"(a[3]), "r"(b0), "r"(b1));
}
__device__ __forceinline__ void split_store(__nv_bfloat16* h, __nv_bfloat16* l,
                                            long long i, float4 v) {
    __nv_bfloat16 h0 = __float2bfloat16(v.x), h1 = __float2bfloat16(v.y);
    __nv_bfloat16 h2 = __float2bfloat16(v.z), h3 = __float2bfloat16(v.w);
    __nv_bfloat16 l0 = __float2bfloat16(v.x - __bfloat162float(h0));
    __nv_bfloat16 l1 = __float2bfloat16(v.y - __bfloat162float(h1));
    __nv_bfloat16 l2 = __float2bfloat16(v.z - __bfloat162float(h2));
    __nv_bfloat16 l3 = __float2bfloat16(v.w - __bfloat162float(h3));
    __nv_bfloat162* hp = reinterpret_cast<__nv_bfloat162*>(h) + 2 * i;
    __nv_bfloat162* lp = reinterpret_cast<__nv_bfloat162*>(l) + 2 * i;
    hp[0] = __halves2bfloat162(h0, h1); hp[1] = __halves2bfloat162(h2, h3);
    lp[0] = __halves2bfloat162(l0, l1); lp[1] = __halves2bfloat162(l2, l3);
}

// ============ 1) split activations (x1 and x2 in one launch) ============
__global__ void split_all_kernel(const float* __restrict__ x1, const float* __restrict__ x2) {
    long long i = (long long)blockIdx.x * blockDim.x + threadIdx.x;  // float4 idx, 0..8388607
    int which = (int)(i >> 22);
    long long li = i & 4194303LL;
    const float* x = which ? x2 : x1;
    float4 v = reinterpret_cast<const float4*>(x)[li];
    split_store(which ? g_x2h : g_x1h, which ? g_x2l : g_x1l, li, v);
}

// ============ 2) split all three weights (flat, no transpose) ============
__global__ void wsplit_all_kernel(const float* __restrict__ Wq, const float* __restrict__ Wk,
                                  const float* __restrict__ Wv) {
    int wi = blockIdx.x >> 10;
    long long i = (long long)(blockIdx.x & 1023) * blockDim.x + threadIdx.x;  // float4 idx
    const float* W = (wi == 0) ? Wq : ((wi == 1) ? Wk : Wv);
    float4 v = reinterpret_cast<const float4*>(W)[i];
    split_store(g_wh + wi * WN, g_wl + wi * WN, i, v);
}

// pad launches so the GEMM is launch #5 (ncu capture window)
__global__ void pad_kernel() {}

// ============ 3) GEMM Y[m][n] = sum_k X[m][k]*W[n][k], bf16x3 mma.sync ============
// 512 threads, warp tile 32x32, 4-stage cp.async ring, ONE __syncthreads per K-step.
#define ROWB 80
#define ARR_B 10240
#define STG_B 40960
#define NSTAGE 4
// total = 4*40960 = 163840 bytes

extern __shared__ __nv_bfloat16 dyn_smem[];

__global__ void __launch_bounds__(512, 1) gemm_mma_kernel() {
    int z = blockIdx.z;
    const __nv_bfloat16* Ah = (z == 0) ? g_x1h : g_x2h;
    const __nv_bfloat16* Al = (z == 0) ? g_x1l : g_x2l;
    const __nv_bfloat16* Bh = g_wh + z * WN;
    const __nv_bfloat16* Bl = g_wl + z * WN;
    float* Y = (z == 0) ? g_Yq : ((z == 1) ? g_Yk : g_Yv);

    int t = threadIdx.x, warp = t >> 5, lane = t & 31;
    int wm = warp & 3, wn = warp >> 2;               // 4x4 warp grid, 32x32 tiles
    int rb = blockIdx.y * 128, cb = blockIdx.x * 128;

    unsigned sb = smem_u32(dyn_smem);

    float acc[2][4][4];
#pragma unroll
    for (int mi = 0; mi < 2; mi++)
#pragma unroll
        for (int nj = 0; nj < 4; nj++)
#pragma unroll
            for (int q = 0; q < 4; q++) acc[mi][nj][q] = 0.f;

    // staging: each thread copies one 16B chunk per array per stage
    int sr = t >> 2, sc = t & 3;                     // row 0..127, chunk 0..3
    const __nv_bfloat16* gA0 = Ah + (rb + sr) * 1024 + sc * 8;
    const __nv_bfloat16* gA1 = Al + (rb + sr) * 1024 + sc * 8;
    const __nv_bfloat16* gB0 = Bh + (cb + sr) * 1024 + sc * 8;
    const __nv_bfloat16* gB1 = Bl + (cb + sr) * 1024 + sc * 8;
    unsigned sdst = (unsigned)(sr * ROWB + sc * 16);

#define STAGE(buf, kt)                                   \
    do {                                                 \
        int _kc = (kt) * 32;                             \
        unsigned _b = sb + (buf) * STG_B + sdst;         \
        cpasync16(_b + 0 * ARR_B, gA0 + _kc);            \
        cpasync16(_b + 1 * ARR_B, gA1 + _kc);            \
        cpasync16(_b + 2 * ARR_B, gB0 + _kc);            \
        cpasync16(_b + 3 * ARR_B, gB1 + _kc);            \
        cpasync_commit();                                \
    } while (0)

    // ldmatrix per-lane address components (identical mapping to R12/R16, verified passing)
    unsigned aRowB = (unsigned)((lane & 15) * ROWB);
    unsigned aColB = (unsigned)((lane >> 4) * 16);
    unsigned bRowB = (unsigned)(((((lane >> 4) & 1) * 8) + (lane & 7)) * ROWB);
    unsigned bColB = (unsigned)(((lane >> 3) & 1) * 16);

    // prologue: stages 0..2 in flight (NSTAGE-1 groups)
    STAGE(0, 0); STAGE(1, 1); STAGE(2, 2);

    for (int kt = 0; kt < 32; kt++) {
        int buf = kt & 3;
        // wait until group kt complete (pending after wait: {kt+1, kt+2} at steady state)
        if (kt <= 29)      cpasync_wait<2>();
        else if (kt == 30) cpasync_wait<1>();
        else               cpasync_wait<0>();
        __syncthreads();   // stage-kt data visible to all; slot (kt+3)&3 free (compute kt-1 done)

        if (kt + 3 < 32) STAGE((kt + 3) & 3, kt + 3);

        unsigned base = sb + buf * STG_B;
#pragma unroll
        for (int k16 = 0; k16 < 2; k16++) {
            unsigned kOff = (unsigned)(k16 * 32);
            unsigned ah[2][4], al[2][4], bh[2][4], bl[2][4];
#pragma unroll
            for (int mi = 0; mi < 2; mi++) {
                unsigned ad = base + (unsigned)((wm * 32 + mi * 16) * ROWB) + aRowB + kOff + aColB;
                ldsm4(ah[mi], ad);
                ldsm4(al[mi], ad + ARR_B);
            }
#pragma unroll
            for (int nt = 0; nt < 2; nt++) {
                unsigned bd = base + 2 * ARR_B + (unsigned)((wn * 32 + nt * 16) * ROWB)
                            + bRowB + kOff + bColB;
                ldsm4(bh[nt], bd);
                ldsm4(bl[nt], bd + ARR_B);
            }
            // term-major: 8 independent MMAs per term -> dependency distance 8
#pragma unroll
            for (int mi = 0; mi < 2; mi++)
#pragma unroll
                for (int nj = 0; nj < 4; nj++)
                    mma_bf16(acc[mi][nj], ah[mi], bh[nj >> 1][(nj & 1) * 2], bh[nj >> 1][(nj & 1) * 2 + 1]);
#pragma unroll
            for (int mi = 0; mi < 2; mi++)
#pragma unroll
                for (int nj = 0; nj < 4; nj++)
                    mma_bf16(acc[mi][nj], ah[mi], bl[nj >> 1][(nj & 1) * 2], bl[nj >> 1][(nj & 1) * 2 + 1]);
#pragma unroll
            for (int mi = 0; mi < 2; mi++)
#pragma unroll
                for (int nj = 0; nj < 4; nj++)
                    mma_bf16(acc[mi][nj], al[mi], bh[nj >> 1][(nj & 1) * 2], bh[nj >> 1][(nj & 1) * 2 + 1]);
        }
        // NOTE: no second __syncthreads — WAR protection comes from next iteration's top sync
    }

    // epilogue: c0,c1 = (row lane/4, col 2*(lane%4)); c2,c3 = row+8
    int erow = lane >> 2, ecol = (lane & 3) * 2;
#pragma unroll
    for (int mi = 0; mi < 2; mi++) {
#pragma unroll
        for (int nj = 0; nj < 4; nj++) {
            int gr = rb + wm * 32 + mi * 16 + erow;
            int gc = cb + wn * 32 + nj * 8 + ecol;
            *reinterpret_cast<float2*>(Y + gr * 1024 + gc) =
                make_float2(acc[mi][nj][0], acc[mi][nj][1]);
            *reinterpret_cast<float2*>(Y + (gr + 8) * 1024 + gc) =
                make_float2(acc[mi][nj][2], acc[mi][nj][3]);
        }
    }
}

// ============ 4) attention: warp per unit (b,i,j); lane = l2 column ============
__global__ void __launch_bounds__(128) attn_kernel(const float* __restrict__ bq,
                                                   const float* __restrict__ bk,
                                                   const float* __restrict__ bv) {
    __shared__ float qs[4][32][33];
    __shared__ float vs[4][32][33];
    int w = threadIdx.x >> 5, lane = threadIdx.x & 31;
    int u = blockIdx.x * 4 + w;
    int b = u >> 10, i = (u >> 5) & 31, j = u & 31;

    const float* Krow = g_Yk + ((b * 32 + i) * 32 + j) * 1024;
    const float* Vrow = g_Yv + ((b * 32 + i) * 32 + j) * 1024;

    float kreg[32];
#pragma unroll
    for (int h = 0; h < 32; h++)
        kreg[h] = Krow[h * 32 + lane] + bk[h * 32 + lane];
#pragma unroll
    for (int r = 0; r < 32; r++)
        vs[w][r][lane] = Vrow[r * 32 + lane] + bv[r * 32 + lane];
#pragma unroll
    for (int r = 0; r < 32; r++)
        qs[w][r][lane] = g_Yq[((b * 32 + lane) * 32 + i) * 1024 + r * 32 + j] + bq[r * 32 + j];
    __syncwarp();

    float a[32];
#pragma unroll
    for (int r = 0; r < 32; r++) {
        float e = 0.f;
#pragma unroll
        for (int h = 0; h < 32; h++) e = fmaf(qs[w][r][h], kreg[h], e);
        float m = e;
#pragma unroll
        for (int o = 16; o > 0; o >>= 1) m = fmaxf(m, __shfl_xor_sync(0xffffffffu, m, o));
        float p = __expf(e - m);
        float s = p;
#pragma unroll
        for (int o = 16; o > 0; o >>= 1) s += __shfl_xor_sync(0xffffffffu, s, o);
        a[r] = p * __frcp_rn(s);
    }

    float* Orow = g_O + ((b * 32 + i) * 32 + j) * 1024;
#pragma unroll
    for (int r = 0; r < 32; r++) {
        float o = 0.f;
#pragma unroll
        for (int t = 0; t < 32; t++) o = fmaf(vs[w][r][t], a[t], o);
        Orow[r * 32 + lane] = o;
    }
}

// ============ 5) output transpose: out[b,j,l, r*32+i] = g_O[b,i,j, r*32+l] ============
__global__ void otrans_kernel(float* __restrict__ out) {
    __shared__ float s[32][33];
    int t = threadIdx.x;
    int b = blockIdx.x >> 5, j = blockIdx.x & 31;
    for (int r = 0; r < 32; r++) {
        __syncthreads();
#pragma unroll
        for (int k = 0; k < 4; k++) {
            int idx = t + k * 256, i = idx >> 5, l = idx & 31;
            s[i][l] = g_O[((b * 32 + i) * 32 + j) * 1024 + r * 32 + l];
        }
        __syncthreads();
#pragma unroll
        for (int k = 0; k < 4; k++) {
            int idx = t + k * 256, l = idx >> 5, i = idx & 31;
            out[((b * 32 + j) * 32 + l) * 1024 + r * 32 + i] = s[i][l];
        }
    }
}

extern "C" void kernel_launch(void* const* d_in, const int* in_sizes, int n_in,
                              void* d_out, int out_size) {
    const float* x1 = (const float*)d_in[0];
    const float* x2 = (const float*)d_in[1];
    const float* Wq = (const float*)d_in[2];
    const float* bq = (const float*)d_in[3];
    const float* Wk = (const float*)d_in[4];
    const float* bk = (const float*)d_in[5];
    const float* Wv = (const float*)d_in[6];
    const float* bv = (const float*)d_in[7];
    float* out = (float*)d_out;

    cudaFuncSetAttribute(gemm_mma_kernel, cudaFuncAttributeMaxDynamicSharedMemorySize,
                         NSTAGE * STG_B);

    split_all_kernel<<<32768, 256>>>(x1, x2);          // launch 1
    wsplit_all_kernel<<<3072, 256>>>(Wq, Wk, Wv);      // launch 2
    pad_kernel<<<1, 32>>>();                           // launch 3
    pad_kernel<<<1, 32>>>();                           // launch 4
    gemm_mma_kernel<<<dim3(8, 128, 3), 512, NSTAGE * STG_B>>>();  // launch 5 <- ncu window
    attn_kernel<<<4096, 128>>>(bq, bk, bv);            // launch 6
    otrans_kernel<<<512, 256>>>(out);                  // launch 7
}